// round 8
// baseline (speedup 1.0000x reference)
#include <cuda_runtime.h>
#include <math_constants.h>

// Problem constants (fixed by the reference setup)
#define NN    50000
#define EE    1600000
#define DIN   128
#define DOUT  128
#define HH    8
#define DHH   16
#define DGG   64
#define BCOLS 352   // padded: 64 zj | 128 f0 | 128 f1 | 8 fz | 24 pad

// ---------------- device scratch (no allocation allowed) ----------------
__device__ float  g_B[DIN * BCOLS];    // prepacked GEMM B
__device__ float  g_zj[NN * DGG];      // feat @ Wpg              [N,64]
__device__ float  g_f0[NN * DOUT];     // relu(feat@W0 + b0)      [N,128]
__device__ float  g_f1[NN * DOUT];     // relu(feat@W1 + b1)      [N,128]
__device__ float  g_fz[NN * HH];       // feat @ wg[192:320]      [N,8]
__device__ float  g_aself[NN * HH];    // leaky(f0 . att_self)    [N,8]
__device__ float  g_aneigh[NN * HH];   // leaky(f1 . att_neigh)   [N,8]
__device__ int    g_cnt[NN];
__device__ int    g_ptr[NN + 1];
__device__ int    g_pos[NN];
__device__ unsigned long long g_edge[EE];  // packed (val<<32 | col), CSR order

// ---------------- CSR build ----------------
__global__ void k_zero_cnt() {
    int i = blockIdx.x * blockDim.x + threadIdx.x;
    if (i < NN) g_cnt[i] = 0;
}

__global__ void k_hist(const int* __restrict__ row) {
    int i = blockIdx.x * blockDim.x + threadIdx.x;
    if (i < EE) atomicAdd(&g_cnt[row[i]], 1);
}

__global__ void k_scan() {
    __shared__ int wsum[32];
    __shared__ int s_carry;
    int tid  = threadIdx.x;
    int lane = tid & 31;
    int wid  = tid >> 5;
    if (tid == 0) s_carry = 0;
    __syncthreads();
    for (int base = 0; base < NN; base += 1024) {
        int i = base + tid;
        int x = (i < NN) ? g_cnt[i] : 0;
        int v = x;
        #pragma unroll
        for (int off = 1; off < 32; off <<= 1) {
            int t = __shfl_up_sync(0xffffffffu, v, off);
            if (lane >= off) v += t;
        }
        if (lane == 31) wsum[wid] = v;
        __syncthreads();
        if (wid == 0) {
            int s = wsum[lane];
            #pragma unroll
            for (int off = 1; off < 32; off <<= 1) {
                int t = __shfl_up_sync(0xffffffffu, s, off);
                if (lane >= off) s += t;
            }
            wsum[lane] = s;
        }
        __syncthreads();
        int incl  = v + (wid > 0 ? wsum[wid - 1] : 0);
        int carry = s_carry;
        if (i < NN) {
            int e = carry + incl - x;
            g_ptr[i] = e;
            g_pos[i] = e;
        }
        __syncthreads();
        if (tid == 1023) s_carry = carry + incl;
        __syncthreads();
    }
    if (tid == 0) g_ptr[NN] = s_carry;
}

__global__ void k_scatter(const int* __restrict__ row,
                          const int* __restrict__ col,
                          const float* __restrict__ val) {
    int i = blockIdx.x * blockDim.x + threadIdx.x;
    if (i < EE) {
        int p = atomicAdd(&g_pos[row[i]], 1);
        unsigned long long pk =
            ((unsigned long long)__float_as_uint(val[i]) << 32) |
            (unsigned long long)(unsigned)col[i];
        g_edge[p] = pk;
    }
}

// ---------------- pack B once: [128][352] ----------------
__global__ void k_pack(const float* __restrict__ Wpg,
                       const float* __restrict__ W,
                       const float* __restrict__ wg) {
    int idx = blockIdx.x * blockDim.x + threadIdx.x;
    if (idx >= DIN * BCOLS) return;
    int k = idx / BCOLS, c = idx - k * BCOLS;
    float w = 0.f;
    if (c < DGG) {
        w = Wpg[k * DGG + c];
    } else if (c < 320) {
        int j  = c - DGG;
        int o  = j >> 7;
        int jj = j & 127;
        int h  = jj >> 4, kb = jj & 15;
        w = W[((o * HH + h) * DIN + k) * DHH + kb];
    } else if (c < 328) {
        w = wg[(192 + k) * HH + (c - 320)];
    }
    g_B[idx] = w;
}

// ---------------- GEMM: [N,128] x [128,352] (packed B) ----------------
#define KC 16
__global__ void __launch_bounds__(256, 2)
k_gemm(const float* __restrict__ feat, const float* __restrict__ b) {
    __shared__ float As[32][KC + 1];
    __shared__ float Bs[KC][BCOLS];
    int tid  = threadIdx.x;
    int row0 = blockIdx.x * 32;
    int rg = tid >> 5;   // warp id -> 4 rows each
    int ct = tid & 31;   // lane -> 11 cols stride 32
    float acc[4][11];
    #pragma unroll
    for (int i = 0; i < 4; i++)
        #pragma unroll
        for (int j = 0; j < 11; j++) acc[i][j] = 0.f;

    for (int kc = 0; kc < DIN; kc += KC) {
        for (int idx = tid; idx < 32 * (KC / 4); idx += 256) {
            int r = idx >> 2, q = idx & 3;
            int gr = row0 + r;
            float4 f = (gr < NN)
                ? *(const float4*)(feat + gr * DIN + kc + q * 4)
                : make_float4(0.f, 0.f, 0.f, 0.f);
            As[r][q * 4 + 0] = f.x; As[r][q * 4 + 1] = f.y;
            As[r][q * 4 + 2] = f.z; As[r][q * 4 + 3] = f.w;
        }
        for (int idx = tid; idx < KC * (BCOLS / 4); idx += 256) {
            int kk = idx / (BCOLS / 4), q = idx - kk * (BCOLS / 4);
            *((float4*)&Bs[kk][q * 4]) =
                *(const float4*)(g_B + (kc + kk) * BCOLS + q * 4);
        }
        __syncthreads();
        #pragma unroll
        for (int kk = 0; kk < KC; kk++) {
            float a[4], bb[11];
            #pragma unroll
            for (int i = 0; i < 4; i++) a[i] = As[rg * 4 + i][kk];
            #pragma unroll
            for (int j = 0; j < 11; j++) bb[j] = Bs[kk][ct + 32 * j];
            #pragma unroll
            for (int i = 0; i < 4; i++)
                #pragma unroll
                for (int j = 0; j < 11; j++) acc[i][j] += a[i] * bb[j];
        }
        __syncthreads();
    }
    #pragma unroll
    for (int i = 0; i < 4; i++) {
        int r = row0 + rg * 4 + i;
        if (r >= NN) continue;
        #pragma unroll
        for (int j = 0; j < 11; j++) {
            int c = ct + 32 * j;
            float v = acc[i][j];
            if (c < DGG) {
                g_zj[r * DGG + c] = v;
            } else if (c < 320) {
                int jj = c - DGG;
                float o = fmaxf(v + b[jj], 0.f);
                if (jj < DOUT) g_f0[r * DOUT + jj] = o;
                else           g_f1[r * DOUT + (jj - DOUT)] = o;
            } else if (c < 328) {
                g_fz[r * HH + (c - 320)] = v;
            }
        }
    }
}

// ---------------- attention scalars ----------------
__device__ __forceinline__ float leaky(float x) {
    return x >= 0.f ? x : 0.2f * x;
}

__global__ void k_att(const float* __restrict__ att) {
    int i = blockIdx.x * blockDim.x + threadIdx.x;
    if (i >= NN * HH) return;
    int n = i >> 3, h = i & 7;
    float s = 0.f, t = 0.f;
    const float* f0p = g_f0 + n * DOUT + h * DHH;
    const float* f1p = g_f1 + n * DOUT + h * DHH;
    const float* ap  = att + h * (2 * DHH);
    #pragma unroll
    for (int k = 0; k < DHH; k++) {
        s += f0p[k] * ap[k];
        t += f1p[k] * ap[DHH + k];
    }
    g_aself[i]  = leaky(s);
    g_aneigh[i] = leaky(t);
}

// ---------------- main kernel: warp-per-node, no smem, no barriers ----------------
// Lane l covers features 4l..4l+3. All per-node reductions are warp shuffles.
__global__ void __launch_bounds__(128, 12)
k_main(const float* __restrict__ feat,
       const float* __restrict__ wg,       // [320,8]
       const float* __restrict__ scale,    // [2,128]
       const float* __restrict__ offset,   // [2,128]
       float* __restrict__ out) {
    int n = blockIdx.x * 4 + (threadIdx.x >> 5);
    if (n >= NN) return;
    int lane  = threadIdx.x & 31;
    int hlane = lane >> 2;                 // head of this lane's 4 features

    int e0 = g_ptr[n], e1 = g_ptr[n + 1];
    int deg = e1 - e0;

    float aself = g_aself[n * HH + hlane];

    float4 acc = make_float4(0.f, 0.f, 0.f, 0.f);
    float4 zm4 = make_float4(-CUDART_INF_F, -CUDART_INF_F, -CUDART_INF_F, -CUDART_INF_F);
    float4 gn4 = make_float4(0.f, 0.f, 0.f, 0.f);

    #pragma unroll 4
    for (int i = e0; i < e1; i++) {
        unsigned long long pk = g_edge[i];           // warp-uniform broadcast
        int   c = (int)(unsigned)(pk & 0xffffffffull);
        float v = __uint_as_float((unsigned)(pk >> 32));
        float a = (aself + g_aneigh[c * HH + hlane]) * v;
        float4 f = *((const float4*)(g_f1 + c * DOUT) + lane);
        acc.x += a * f.x; acc.y += a * f.y;
        acc.z += a * f.z; acc.w += a * f.w;
        if (lane < 16) {
            float4 z = *((const float4*)(g_zj + c * DGG) + lane);
            zm4.x = fmaxf(zm4.x, z.x); zm4.y = fmaxf(zm4.y, z.y);
            zm4.z = fmaxf(zm4.z, z.z); zm4.w = fmaxf(zm4.w, z.w);
        }
        if (lane < 2) {
            float4 g = *((const float4*)(g_fz + c * HH) + lane);
            gn4.x += v * g.x; gn4.y += v * g.y;
            gn4.z += v * g.z; gn4.w += v * g.w;
        }
    }

    // ---- gate: part[h] = sum_j concat[j]*wg[j][h] (features j = 4*lane..4*lane+3) ----
    float4 fv = *((const float4*)(feat + n * DIN) + lane);
    float part[8];
    #pragma unroll
    for (int hh = 0; hh < 8; hh++) part[hh] = 0.f;
    {
        int j0 = lane * 4;
        const float* wr0 = wg + (j0 + 0) * 8;
        const float* wr1 = wg + (j0 + 1) * 8;
        const float* wr2 = wg + (j0 + 2) * 8;
        const float* wr3 = wg + (j0 + 3) * 8;
        #pragma unroll
        for (int hh = 0; hh < 8; hh++)
            part[hh] += fv.x * wr0[hh] + fv.y * wr1[hh]
                      + fv.z * wr2[hh] + fv.w * wr3[hh];
    }
    if (lane < 16) {
        float zx = (deg > 0) ? zm4.x : 0.f;
        float zy = (deg > 0) ? zm4.y : 0.f;
        float zz = (deg > 0) ? zm4.z : 0.f;
        float zw = (deg > 0) ? zm4.w : 0.f;
        int j0 = lane * 4;                     // zmax feature 0..63
        const float* wr0 = wg + (128 + j0 + 0) * 8;
        const float* wr1 = wg + (128 + j0 + 1) * 8;
        const float* wr2 = wg + (128 + j0 + 2) * 8;
        const float* wr3 = wg + (128 + j0 + 3) * 8;
        #pragma unroll
        for (int hh = 0; hh < 8; hh++)
            part[hh] += zx * wr0[hh] + zy * wr1[hh]
                      + zz * wr2[hh] + zw * wr3[hh];
    }
    #pragma unroll
    for (int hh = 0; hh < 8; hh++) {
        #pragma unroll
        for (int off = 16; off > 0; off >>= 1)
            part[hh] += __shfl_xor_sync(0xffffffffu, part[hh], off);
    }
    // nmean-linearized contribution: lane0 gn4 = heads 0..3, lane1 gn4 = heads 4..7
    float g0 = __shfl_sync(0xffffffffu, gn4.x, 0);
    float g1 = __shfl_sync(0xffffffffu, gn4.y, 0);
    float g2 = __shfl_sync(0xffffffffu, gn4.z, 0);
    float g3 = __shfl_sync(0xffffffffu, gn4.w, 0);
    float g4 = __shfl_sync(0xffffffffu, gn4.x, 1);
    float g5 = __shfl_sync(0xffffffffu, gn4.y, 1);
    float g6 = __shfl_sync(0xffffffffu, gn4.z, 1);
    float g7 = __shfl_sync(0xffffffffu, gn4.w, 1);
    float gate0 = part[0] + g0, gate1 = part[1] + g1;
    float gate2 = part[2] + g2, gate3 = part[3] + g3;
    float gate4 = part[4] + g4, gate5 = part[5] + g5;
    float gate6 = part[6] + g6, gate7 = part[7] + g7;
    float gsel = (hlane == 0) ? gate0 : (hlane == 1) ? gate1
               : (hlane == 2) ? gate2 : (hlane == 3) ? gate3
               : (hlane == 4) ? gate4 : (hlane == 5) ? gate5
               : (hlane == 6) ? gate6 : gate7;

    // ---- norm + output ----
    float4 f0v = *((const float4*)(g_f0 + n * DOUT) + lane);
    float4 h1;
    h1.x = acc.x * gsel; h1.y = acc.y * gsel;
    h1.z = acc.z * gsel; h1.w = acc.w * gsel;

    float s0 = f0v.x + f0v.y + f0v.z + f0v.w;
    float q0 = f0v.x * f0v.x + f0v.y * f0v.y + f0v.z * f0v.z + f0v.w * f0v.w;
    float s1 = h1.x + h1.y + h1.z + h1.w;
    float q1 = h1.x * h1.x + h1.y * h1.y + h1.z * h1.z + h1.w * h1.w;
    #pragma unroll
    for (int off = 16; off > 0; off >>= 1) {
        s0 += __shfl_xor_sync(0xffffffffu, s0, off);
        q0 += __shfl_xor_sync(0xffffffffu, q0, off);
        s1 += __shfl_xor_sync(0xffffffffu, s1, off);
        q1 += __shfl_xor_sync(0xffffffffu, q1, off);
    }
    float mu0 = s0 * (1.f / DOUT);
    float mu1 = s1 * (1.f / DOUT);
    float r0  = rsqrtf(q0 * (1.f / DOUT) - mu0 * mu0 + 1e-9f);
    float r1  = rsqrtf(q1 * (1.f / DOUT) - mu1 * mu1 + 1e-9f);

    float4 sc0 = *((const float4*)(scale)        + lane);
    float4 sc1 = *((const float4*)(scale + DOUT) + lane);
    float4 of0 = *((const float4*)(offset)        + lane);
    float4 of1 = *((const float4*)(offset + DOUT) + lane);

    float4 o;
    o.x = (f0v.x - mu0) * r0 * sc0.x + of0.x + (h1.x - mu1) * r1 * sc1.x + of1.x;
    o.y = (f0v.y - mu0) * r0 * sc0.y + of0.y + (h1.y - mu1) * r1 * sc1.y + of1.y;
    o.z = (f0v.z - mu0) * r0 * sc0.z + of0.z + (h1.z - mu1) * r1 * sc1.z + of1.z;
    o.w = (f0v.w - mu0) * r0 * sc0.w + of0.w + (h1.w - mu1) * r1 * sc1.w + of1.w;
    *((float4*)(out + n * DOUT) + lane) = o;
}

// ---------------- launch ----------------
extern "C" void kernel_launch(void* const* d_in, const int* in_sizes, int n_in,
                              void* d_out, int out_size) {
    const int*   row    = (const int*)d_in[0];
    const int*   col    = (const int*)d_in[1];
    const float* val    = (const float*)d_in[2];
    const float* feat   = (const float*)d_in[3];
    const float* W      = (const float*)d_in[4];
    const float* b      = (const float*)d_in[5];
    const float* att    = (const float*)d_in[6];
    const float* offset = (const float*)d_in[7];
    const float* scale  = (const float*)d_in[8];
    const float* wg     = (const float*)d_in[9];
    const float* wpg    = (const float*)d_in[10];
    float* out = (float*)d_out;

    // CSR build
    k_zero_cnt<<<(NN + 255) / 256, 256>>>();
    k_hist<<<(EE + 255) / 256, 256>>>(row);
    k_scan<<<1, 1024>>>();
    k_scatter<<<(EE + 255) / 256, 256>>>(row, col, val);

    // Dense projections
    k_pack<<<(DIN * BCOLS + 255) / 256, 256>>>(wpg, W, wg);
    k_gemm<<<(NN + 31) / 32, 256>>>(feat, b);
    k_att<<<(NN * HH + 255) / 256, 256>>>(att);

    // Fused aggregate + gate + norm + output (warp per node)
    k_main<<<(NN + 3) / 4, 128>>>(feat, wg, scale, offset, out);
}